// round 17
// baseline (speedup 1.0000x reference)
#include <cuda_runtime.h>
#include <cuda_fp16.h>
#include <cstdint>

#define NN 12288
#define INFEAT 128
#define OF 64
#define AL 0.2f

#define JSPLIT 3
#define KSL (NN/JSPLIT)   /* 4096 */
#define KT 64
#define NT (KSL/KT)       /* 64 */
#define RB 128
#define NRB (NN/RB)       /* 96 */
#define NGT (NN/KT)       /* 192 */
#define PSTR 68
#define HTB 8192          /* one H variant tile: 64 rows x 128B */
#define HTILE (2*HTB)     /* hi + lo */

/* smem layout (relative to 1024-aligned base) */
#define SP_PHI 0
#define SP_H   16384
#define SP_RC  32768
#define SMEM_DYN (32768 + 2048 + 1024)

// ---------------- device scratch ----------------
__device__ __align__(16) float  g_h[NN * OF];
__device__ float  g_c[NN];
__device__ float  g_d[NN];
__device__ __align__(16) float4 g_rowc[NN];   // (-c, A, A', 0)
__device__ __align__(16) float4 g_scalJ[NN];  // (d, B, B', 0)
__device__ __align__(16) float  g_part[(size_t)JSPLIT * NN * PSTR];
__device__ __align__(16) unsigned char g_Ht[(size_t)NGT * HTILE];  // 3 MB
__device__ unsigned g_dmax_enc;

// ---------------- helpers ----------------
__device__ __forceinline__ unsigned fenc(float f) {
    unsigned b = __float_as_uint(f);
    return (b & 0x80000000u) ? ~b : (b | 0x80000000u);
}
__device__ __forceinline__ float fdec(unsigned u) {
    return (u & 0x80000000u) ? __uint_as_float(u & 0x7fffffffu)
                             : __uint_as_float(~u);
}
__device__ __forceinline__ unsigned su(const void* p) {
    unsigned r;
    asm("{ .reg .u64 t; cvta.to.shared.u64 t, %1; cvt.u32.u64 %0, t; }"
        : "=r"(r) : "l"(p));
    return r;
}
__device__ __forceinline__ void ldsm4(unsigned* r, unsigned a) {
    asm volatile("ldmatrix.sync.aligned.m8n8.x4.shared.b16 {%0,%1,%2,%3}, [%4];"
                 : "=r"(r[0]), "=r"(r[1]), "=r"(r[2]), "=r"(r[3]) : "r"(a));
}
__device__ __forceinline__ void mma16816(float* c, const unsigned* a,
                                         unsigned b0, unsigned b1) {
    asm volatile("mma.sync.aligned.m16n8k16.row.col.f32.f16.f16.f32 "
                 "{%0,%1,%2,%3}, {%4,%5,%6,%7}, {%8,%9}, {%0,%1,%2,%3};"
                 : "+f"(c[0]), "+f"(c[1]), "+f"(c[2]), "+f"(c[3])
                 : "r"(a[0]), "r"(a[1]), "r"(a[2]), "r"(a[3]),
                   "r"(b0), "r"(b1));
}

// ---------------- K0 ----------------
__global__ void k_reset() { g_dmax_enc = 0u; }

// ---------------- K1: h = input @ W ----------------
__global__ void __launch_bounds__(256) k_linear(const float* __restrict__ x,
                                                const float* __restrict__ W) {
    __shared__ __align__(16) float Wsm[INFEAT * OF];
    __shared__ __align__(16) float Xsm[16 * INFEAT];
    int tid = threadIdx.x, i0 = blockIdx.x * 16;
    const float4* Wg = (const float4*)W;
    float4* Ws4 = (float4*)Wsm;
    #pragma unroll
    for (int e = tid; e < INFEAT * OF / 4; e += 256) Ws4[e] = Wg[e];
    const float4* Xg = (const float4*)(x + (size_t)i0 * INFEAT);
    float4* Xs4 = (float4*)Xsm;
    #pragma unroll
    for (int e = tid; e < 16 * INFEAT / 4; e += 256) Xs4[e] = Xg[e];
    __syncthreads();
    int f = tid & 63, rt = tid >> 6;
    float acc[4] = {0.f, 0.f, 0.f, 0.f};
    #pragma unroll 4
    for (int k = 0; k < INFEAT; k++) {
        float w = Wsm[k * OF + f];
        #pragma unroll
        for (int j = 0; j < 4; j++) acc[j] += Xsm[(rt * 4 + j) * INFEAT + k] * w;
    }
    #pragma unroll
    for (int j = 0; j < 4; j++) g_h[(size_t)(i0 + rt * 4 + j) * OF + f] = acc[j];
}

// ---------------- K2: c, d, dmax ----------------
__global__ void __launch_bounds__(256) k_attvec(const float* __restrict__ a) {
    __shared__ float sred[8];
    int tid = threadIdx.x, lane = tid & 31, wid = tid >> 5;
    int i = blockIdx.x * 8 + wid;
    float h0 = g_h[(size_t)i * OF + lane];
    float h1 = g_h[(size_t)i * OF + 32 + lane];
    float c = h0 * __ldg(a + lane) + h1 * __ldg(a + 32 + lane);
    float d = h0 * __ldg(a + 64 + lane) + h1 * __ldg(a + 96 + lane);
    #pragma unroll
    for (int s = 16; s; s >>= 1) {
        c += __shfl_xor_sync(0xffffffffu, c, s);
        d += __shfl_xor_sync(0xffffffffu, d, s);
    }
    if (lane == 0) { g_c[i] = c; g_d[i] = d; sred[wid] = d; }
    __syncthreads();
    if (tid == 0) {
        float m = sred[0];
        #pragma unroll
        for (int w = 1; w < 8; w++) m = fmaxf(m, sred[w]);
        atomicMax(&g_dmax_enc, fenc(m));
    }
}

// ---------------- K3: softmax factors ----------------
__global__ void __launch_bounds__(256) k_factors() {
    int i = blockIdx.x * 256 + threadIdx.x;
    float dmax = fdec(g_dmax_enc);
    float c = g_c[i], d = g_d[i];
    float cm = c + dmax;
    float s = cm > 0.f ? cm : AL * cm;
    g_rowc[i]  = make_float4(-c, expf(cm - s), expf(AL * cm - s), 0.f);
    float dm = d - dmax;
    g_scalJ[i] = make_float4(d, expf(dm), expf(AL * dm), 0.f);
}

// ---------------- K3b: H tiles [n64][k64] fp16 hi/lo, pre-swizzled ----
__global__ void __launch_bounds__(128) k_hprep() {
    int gt = blockIdx.x;
    size_t tb = (size_t)gt * HTILE;
    for (int e = threadIdx.x; e < OF * 64; e += 128) {
        int n = e >> 6, k = e & 63;
        float hv = g_h[(size_t)(gt * KT + k) * OF + n];
        __half hh = __float2half_rn(hv);
        __half hl = __float2half_rn(hv - __half2float(hh));
        unsigned off = (unsigned)(n * 128 + k * 2);
        unsigned sw = off ^ ((off >> 3) & 0x70);
        *(__half*)(g_Ht + tb + sw) = hh;
        *(__half*)(g_Ht + tb + HTB + sw) = hl;
    }
}

// ---------------- K4: main — P build + 2-product HMMA GEMM ----------------
__global__ void __launch_bounds__(256, 2) k_main(const int* __restrict__ adj) {
    extern __shared__ char dynsm[];
    char* sb = (char*)((((uintptr_t)dynsm) + 1023u) & ~(uintptr_t)1023u);
    unsigned base = su(sb);
    int tid = threadIdx.x, lane = tid & 31, w = tid >> 5;
    int rowbase = blockIdx.x * RB, js = blockIdx.y;

    // stage row factors once
    if (tid < RB) ((float4*)(sb + SP_RC))[tid] = __ldg(&g_rowc[rowbase + tid]);

    // phase-1 ids: 16 threads cover one row's 64-col chunk (4 int4 each)
    int c16 = tid & 15;      // int4 chunk within row (4 j's)
    int rsub = tid >> 4;     // 0..15

    // A-frag address constants (m16k16 ldmatrix.x4)
    int mA = w * 16 + ((lane >> 3) & 1) * 8 + (lane & 7);
    unsigned offA0 = (unsigned)(mA * 128 + (lane >> 4) * 16);
    unsigned xA = (unsigned)((mA & 7) << 4);
    // B-frag lane decomposition
    int nrow_in = lane & 7;
    int half_n = (lane >> 4) & 1;
    int kcB = (lane >> 3) & 1;

    float acc[8][4];
    #pragma unroll
    for (int i = 0; i < 8; i++)
        #pragma unroll
        for (int q = 0; q < 4; q++) acc[i][q] = 0.f;
    float dacc[8];
    #pragma unroll
    for (int i = 0; i < 8; i++) dacc[i] = 0.f;

    const int4* adj4 = (const int4*)adj;
    const size_t rowstr = NN / 4;
    const size_t abase0 = (size_t)(rowbase + rsub) * rowstr + (size_t)c16;

    for (int T = 0; T < NT; T++) {
        int gt = js * NT + T;
        int j0 = gt * KT;
        __syncthreads();

        // adj prefetch: 8 coalesced int4 (MLP=8)
        int4 av[8];
        {
            size_t ab = abase0 + (size_t)(j0 >> 2);
            #pragma unroll
            for (int p = 0; p < 8; p++)
                av[p] = __ldg(adj4 + ab + (size_t)(p * 16) * rowstr);
        }

        // copy pre-swizzled H tile (hi+lo, 16 KB, L2-hot)
        {
            const float4* src = (const float4*)(g_Ht + (size_t)gt * HTILE);
            float4* dst = (float4*)(sb + SP_H);
            #pragma unroll
            for (int e = tid; e < HTILE / 16; e += 256) dst[e] = __ldg(src + e);
        }

        // column factors for this thread's 4 j's
        float4 sc[4];
        #pragma unroll
        for (int e = 0; e < 4; e++) sc[e] = __ldg(&g_scalJ[j0 + c16 * 4 + e]);

        // build P tile (single fp16) in smem + fp32 den in registers
        #pragma unroll
        for (int p = 0; p < 8; p++) {
            int m = p * 16 + rsub;
            float4 rc = ((const float4*)(sb + SP_RC))[m];
            int ai[4] = {av[p].x, av[p].y, av[p].z, av[p].w};
            float pv[4];
            #pragma unroll
            for (int e = 0; e < 4; e++) {
                bool pos = sc[e].x > rc.x;            // d_j > -c_i
                float fa = pos ? rc.y : rc.z;
                float fb = pos ? sc[e].y : sc[e].z;
                pv[e] = (ai[e] != 0) ? fa * fb : 0.f;
            }
            dacc[p] += (pv[0] + pv[1]) + (pv[2] + pv[3]);
            __half h0 = __float2half_rn(pv[0]), h1 = __float2half_rn(pv[1]);
            __half h2 = __float2half_rn(pv[2]), h3 = __float2half_rn(pv[3]);
            unsigned hi01 = (unsigned)__half_as_ushort(h0) |
                            ((unsigned)__half_as_ushort(h1) << 16);
            unsigned hi23 = (unsigned)__half_as_ushort(h2) |
                            ((unsigned)__half_as_ushort(h3) << 16);
            unsigned off = (unsigned)(m * 128 + c16 * 8);
            unsigned sw = off ^ ((off >> 3) & 0x70);
            asm volatile("st.shared.v2.b32 [%0], {%1,%2};"
                         :: "r"(base + SP_PHI + sw), "r"(hi01), "r"(hi23) : "memory");
        }
        __syncthreads();

        // MMA phase: 4 k-steps x 8 feat n-tiles, 2 products (P * (H_hi + H_lo))
        #pragma unroll
        for (int s = 0; s < 4; s++) {
            unsigned aoff = (offA0 + (unsigned)(s * 32)) ^ xA;
            unsigned ahi[4];
            ldsm4(ahi, base + SP_PHI + aoff);
            #pragma unroll
            for (int pi = 0; pi < 4; pi++) {
                int nB = pi * 16 + half_n * 8 + nrow_in;
                unsigned offB = (unsigned)(nB * 128 + kcB * 16 + s * 32);
                unsigned aB = offB ^ (unsigned)((nB & 7) << 4);
                unsigned bhi[4], blo[4];
                ldsm4(bhi, base + SP_H + aB);
                ldsm4(blo, base + SP_H + HTB + aB);
                mma16816(acc[2 * pi],     ahi, bhi[0], bhi[1]);
                mma16816(acc[2 * pi],     ahi, blo[0], blo[1]);
                mma16816(acc[2 * pi + 1], ahi, bhi[2], bhi[3]);
                mma16816(acc[2 * pi + 1], ahi, blo[2], blo[3]);
            }
        }
    }

    // ---- epilogue: write partials (unique writer per element) ----
    float* pt = g_part + (size_t)js * NN * PSTR;
    {
        int r0 = rowbase + w * 16 + (lane >> 2);
        int r1 = r0 + 8;
        int cb = (lane & 3) * 2;
        #pragma unroll
        for (int nn = 0; nn < 8; nn++) {
            *(float2*)(pt + (size_t)r0 * PSTR + nn * 8 + cb) =
                make_float2(acc[nn][0], acc[nn][1]);
            *(float2*)(pt + (size_t)r1 * PSTR + nn * 8 + cb) =
                make_float2(acc[nn][2], acc[nn][3]);
        }
    }
    // den: 16-lane segment reduce (segment == one (p-row, rsub) group)
    #pragma unroll
    for (int p = 0; p < 8; p++) {
        float v = dacc[p];
        v += __shfl_down_sync(0xffffffffu, v, 8, 16);
        v += __shfl_down_sync(0xffffffffu, v, 4, 16);
        v += __shfl_down_sync(0xffffffffu, v, 2, 16);
        v += __shfl_down_sync(0xffffffffu, v, 1, 16);
        if (c16 == 0)
            pt[(size_t)(rowbase + p * 16 + rsub) * PSTR + OF] = v;
    }
}

// ---------------- K5: reduce partials, divide, elu ----------------
__global__ void __launch_bounds__(256) k_out(float* __restrict__ out) {
    int idx = blockIdx.x * 256 + threadIdx.x;
    int row = idx >> 6, f = idx & 63;
    size_t bpos = (size_t)row * PSTR;
    float num = 0.f, den = 0.f;
    #pragma unroll
    for (int js = 0; js < JSPLIT; js++) {
        const float* p = g_part + (size_t)js * NN * PSTR + bpos;
        num += p[f];
        den += p[OF];
    }
    float v = num / den;
    out[idx] = v > 0.f ? v : expm1f(v);
}

// ---------------- launch ----------------
extern "C" void kernel_launch(void* const* d_in, const int* in_sizes, int n_in,
                              void* d_out, int out_size) {
    (void)out_size;
    const float* input = nullptr;
    const int*   adj   = nullptr;
    const float* W     = nullptr;
    const float* a     = nullptr;
    for (int i = 0; i < n_in; i++) {
        switch (in_sizes[i]) {
            case NN * INFEAT: input = (const float*)d_in[i]; break;
            case INFEAT * OF: W     = (const float*)d_in[i]; break;
            case 2 * OF:      a     = (const float*)d_in[i]; break;
            default:
                if ((long long)in_sizes[i] == (long long)NN * NN)
                    adj = (const int*)d_in[i];
                break;
        }
    }
    if (!input) input = (const float*)d_in[0];
    if (!adj)   adj   = (const int*)d_in[1];
    if (!W)     W     = (const float*)d_in[2];
    if (!a)     a     = (const float*)d_in[3];

    cudaFuncSetAttribute(k_main, cudaFuncAttributeMaxDynamicSharedMemorySize,
                         SMEM_DYN);

    k_reset<<<1, 1>>>();
    k_linear<<<NN / 16, 256>>>(input, W);
    k_attvec<<<NN / 8, 256>>>(a);
    k_factors<<<NN / 256, 256>>>();
    k_hprep<<<NGT, 128>>>();
    k_main<<<dim3(NRB, JSPLIT), 256, SMEM_DYN>>>(adj);
    k_out<<<NN * OF / 256, 256>>>((float*)d_out);
}